// round 10
// baseline (speedup 1.0000x reference)
#include <cuda_runtime.h>
#include <cstdint>

#define B_DIM 4096
#define F_DIM 16384
#define G_DIM 512
#define S_DIM 32
#define N_IDX (G_DIM * S_DIM)     // 16384 == F_DIM: idx is a permutation of features

#define SCATTER_BLOCKS 64          // 64 * 256 = 16384 threads, one per index
#define TOTAL_BLOCKS (SCATTER_BLOCKS + B_DIM)

// Folded per-feature weight pw[f] = w_group[j]*fc_kernel[j/S] where idx[j]==f.
// group_idx is a permutation of [0, F): every slot overwritten each launch,
// so no zeroing and no atomics needed for pw itself.
__device__ float        g_pw[F_DIM];
__device__ unsigned int g_scatter_done;   // producer blocks completed (0..64)
__device__ unsigned int g_rows_done;      // consumer blocks completed (0..4096)
// Both counters are reset to 0 by the LAST row block each launch, so every
// graph replay starts from identical state (deterministic, no static guards).

__global__ void __launch_bounds__(256) fused_kernel(const unsigned int* __restrict__ idx_words,
                                                    const float* __restrict__ w_group,
                                                    const float* __restrict__ fc_kernel,
                                                    const float* __restrict__ x,
                                                    float* __restrict__ out) {
    const int tid = threadIdx.x;

    if (blockIdx.x < SCATTER_BLOCKS) {
        // ── Producer: fold weights into pw, then signal ──────────────────
        // Dtype detection: JAX may hand int32 despite int64 in the reference
        // (little-endian int64 < 2^31 has every odd 32-bit word == 0).
        __shared__ int s_is64;
        if (tid == 0) {
            int is64 = 1;
            #pragma unroll
            for (int j = 0; j < 32; j++) {
                if (idx_words[2 * j + 1] != 0u) { is64 = 0; break; }
            }
            s_is64 = is64;
        }
        __syncthreads();

        int j = blockIdx.x * 256 + tid;   // j in [0, N_IDX)
        int g = j / S_DIM;
        float w = w_group[j] * fc_kernel[g];  // UNITS == 1
        long long f;
        if (s_is64) {
            f = ((const long long*)idx_words)[j];
        } else {
            f = (long long)((const int*)idx_words)[j];
        }
        if (f >= 0 && f < F_DIM) {
            g_pw[(int)f] = w;   // permutation: exactly one writer per slot
        }

        // Release: make pw visible, then count this block done.
        __syncthreads();
        if (tid == 0) {
            __threadfence();
            atomicAdd(&g_scatter_done, 1u);
        }
        return;
    }

    // ── Consumer: one block per row b ────────────────────────────────────
    const int b = blockIdx.x - SCATTER_BLOCKS;
    const float4* __restrict__ xr = reinterpret_cast<const float4*>(x + (size_t)b * F_DIM);
    const float4* __restrict__ pw = reinterpret_cast<const float4*>(g_pw);

    // Acquire: wait until all producer blocks have published pw.
    if (tid == 0) {
        while (atomicAdd(&g_scatter_done, 0u) < SCATTER_BLOCKS) {
            __nanosleep(64);
        }
    }
    __syncthreads();
    __threadfence();   // order pw reads after the flag read

    float acc = 0.0f;
    // F/4 = 4096 float4; 256 threads -> 16 iterations each
    #pragma unroll 16
    for (int i = tid; i < F_DIM / 4; i += 256) {
        float4 a = __ldcs(&xr[i]);   // streaming: x is read exactly once
        float4 w = __ldg(&pw[i]);    // pw is hot in L2/L1
        acc += a.x * w.x + a.y * w.y + a.z * w.z + a.w * w.w;
    }

    // Warp reduce
    #pragma unroll
    for (int off = 16; off > 0; off >>= 1)
        acc += __shfl_down_sync(0xFFFFFFFFu, acc, off);

    // Block reduce across 8 warps
    __shared__ float warp_sum[8];
    int wid = tid >> 5, lid = tid & 31;
    if (lid == 0) warp_sum[wid] = acc;
    __syncthreads();
    if (wid == 0) {
        float v = (lid < 8) ? warp_sum[lid] : 0.0f;
        #pragma unroll
        for (int off = 4; off > 0; off >>= 1)
            v += __shfl_down_sync(0xFFFFFFFFu, v, off);
        if (lid == 0) out[b] = v;
    }

    // Epilogue: last row block restores counters to 0 for the next replay.
    __syncthreads();
    if (tid == 0) {
        unsigned int prev = atomicAdd(&g_rows_done, 1u);
        if (prev == B_DIM - 1) {
            g_rows_done = 0u;
            g_scatter_done = 0u;
            __threadfence();
        }
    }
}

extern "C" void kernel_launch(void* const* d_in, const int* in_sizes, int n_in,
                              void* d_out, int out_size) {
    const float* x         = (const float*)d_in[0];
    const void*  group_idx = d_in[1];
    const float* w_group   = (const float*)d_in[2];
    const float* fc_kernel = (const float*)d_in[3];
    float* out = (float*)d_out;

    fused_kernel<<<TOTAL_BLOCKS, 256>>>(
        (const unsigned int*)group_idx, w_group, fc_kernel, x, out);
}